// round 15
// baseline (speedup 1.0000x reference)
#include <cuda_runtime.h>
#include <cuda_bf16.h>
#include <math.h>

#define NN 50000
#define NE 500000
#define NG 2000

typedef unsigned long long u64t;

// ---------------- scratch (device globals) ----------------
__device__ float f_x1  [NN * 128];
__device__ float f_p   [NN * 128];
__device__ float f_h   [NN * 128];
__device__ float f_xcur[NN * 128];
__device__ float f_gi  [NN * 3 * 128];
__device__ float f_as  [NN];
__device__ float f_ad  [NN];
__device__ float g_agg [NG * 128];
__device__ float g_buf [NG * 256];    // [out(128) | hh(128)] per graph
__device__ float g_gi  [NG * 4 * 128];
__device__ int c_cnt[NN];
__device__ int c_off[NN + 1];
__device__ int c_pos[NN];
__device__ int c_eid[NE];
__device__ int c_part[64];

__device__ __forceinline__ float sigm(float x) { return 1.0f / (1.0f + expf(-x)); }

__device__ __forceinline__ void ldm4(unsigned* r, unsigned addr) {
    asm volatile("ldmatrix.sync.aligned.m8n8.x4.shared.b16 {%0,%1,%2,%3}, [%4];"
        : "=r"(r[0]), "=r"(r[1]), "=r"(r[2]), "=r"(r[3]) : "r"(addr));
}
__device__ __forceinline__ void mma16816(float* c, const unsigned* a, const unsigned* b) {
    asm volatile("mma.sync.aligned.m16n8k16.row.col.f32.bf16.bf16.f32 "
        "{%0,%1,%2,%3}, {%4,%5,%6,%7}, {%8,%9}, {%0,%1,%2,%3};"
        : "+f"(c[0]), "+f"(c[1]), "+f"(c[2]), "+f"(c[3])
        : "r"(a[0]), "r"(a[1]), "r"(a[2]), "r"(a[3]), "r"(b[0]), "r"(b[1]));
}
__device__ __forceinline__ void bf16split4(float4 v, unsigned* ph_, unsigned* pl_) {
    __nv_bfloat16 h0 = __float2bfloat16(v.x), h1 = __float2bfloat16(v.y);
    __nv_bfloat16 h2 = __float2bfloat16(v.z), h3 = __float2bfloat16(v.w);
    __nv_bfloat16 l0 = __float2bfloat16(v.x - __bfloat162float(h0));
    __nv_bfloat16 l1 = __float2bfloat16(v.y - __bfloat162float(h1));
    __nv_bfloat16 l2 = __float2bfloat16(v.z - __bfloat162float(h2));
    __nv_bfloat16 l3 = __float2bfloat16(v.w - __bfloat162float(h3));
    __nv_bfloat162 hA, hB, lA, lB;
    hA.x = h0; hA.y = h1; hB.x = h2; hB.y = h3;
    lA.x = l0; lA.y = l1; lB.x = l2; lB.y = l3;
    ph_[0] = *(unsigned*)&hA; ph_[1] = *(unsigned*)&hB;
    pl_[0] = *(unsigned*)&lA; pl_[1] = *(unsigned*)&lB;
}

// ---------------- CSR build ----------------
__global__ void zero_i_kernel(int* p, int n) {
    int t = blockIdx.x * blockDim.x + threadIdx.x;
    if (t < n) p[t] = 0;
}
__global__ void hist_kernel(const int* __restrict__ dst, int* __restrict__ cnt) {
    int e = blockIdx.x * blockDim.x + threadIdx.x;
    if (e < NE) atomicAdd(&cnt[dst[e]], 1);
}
__global__ void __launch_bounds__(256) scan_part_kernel(const int* __restrict__ cnt,
                                                        int* __restrict__ part) {
    __shared__ int sm[256];
    int base = blockIdx.x * 1024;
    int s = 0;
    for (int i = threadIdx.x; i < 1024; i += 256) {
        int idx = base + i;
        s += (idx < NN) ? cnt[idx] : 0;
    }
    sm[threadIdx.x] = s;
    __syncthreads();
    for (int d = 128; d; d >>= 1) {
        if (threadIdx.x < d) sm[threadIdx.x] += sm[threadIdx.x + d];
        __syncthreads();
    }
    if (threadIdx.x == 0) part[blockIdx.x] = sm[0];
}
__global__ void scan_mid_kernel(int* part, int npart) {
    if (threadIdx.x == 0) {
        int run = 0;
        for (int i = 0; i < npart; ++i) { int v = part[i]; part[i] = run; run += v; }
    }
}
__global__ void __launch_bounds__(256) scan_final_kernel(const int* __restrict__ cnt,
                                                         const int* __restrict__ part,
                                                         int* __restrict__ off,
                                                         int* __restrict__ pos) {
    __shared__ int wsum[8];
    int base = blockIdx.x * 1024;
    int lane = threadIdx.x & 31, wid = threadIdx.x >> 5;
    int v[4]; int s = 0;
    int i0 = base + threadIdx.x * 4;
#pragma unroll
    for (int i = 0; i < 4; ++i) {
        int idx = i0 + i;
        v[i] = (idx < NN) ? cnt[idx] : 0;
        s += v[i];
    }
    int ps = s;
#pragma unroll
    for (int o = 1; o < 32; o <<= 1) {
        int t = __shfl_up_sync(0xFFFFFFFFu, ps, o);
        if (lane >= o) ps += t;
    }
    if (lane == 31) wsum[wid] = ps;
    __syncthreads();
    if (threadIdx.x == 0) {
        int run = 0;
#pragma unroll
        for (int w = 0; w < 8; ++w) { int t = wsum[w]; wsum[w] = run; run += t; }
    }
    __syncthreads();
    int excl = ps - s + wsum[wid] + part[blockIdx.x];
#pragma unroll
    for (int i = 0; i < 4; ++i) {
        int idx = i0 + i;
        if (idx < NN) { off[idx] = excl; pos[idx] = excl; }
        excl += v[i];
    }
    if (blockIdx.x == 0 && threadIdx.x == 0) off[NN] = NE;
}
__global__ void fill_kernel(const int* __restrict__ dst, int* __restrict__ pos,
                            int* __restrict__ eid) {
    int e = blockIdx.x * blockDim.x + threadIdx.x;
    if (e < NE) {
        int idx = atomicAdd(&pos[dst[e]], 1);
        eid[idx] = e;
    }
}

// ---------------- dense GEMM JPT=1 generic -----------------
// A rows stride astA; optional A2 (added, stride astA2); DUAL: weight row k<128
// from W, k>=128 from W2 (K must be 256); bias2 added when non-null.
template <int K, int ACT, int DUAL>
__global__ void __launch_bounds__(128) dense_kernel(
    const float* __restrict__ A, const float* __restrict__ A2,
    const float* __restrict__ W, const float* __restrict__ W2,
    const float* __restrict__ bias, const float* __restrict__ bias2,
    float* __restrict__ out,
    int n, int Jtotal, int wstride, int astA, int astA2)
{
    constexpr int KP = K + 4;
    constexpr int NT = 16;
    constexpr int NPRE = NT * K / 512;
    constexpr int KC4 = K / 4;
    extern __shared__ float sm[];
    float* Ws  = sm;
    float* ins = sm + 128 * KP;
    const int tid = threadIdx.x;
    const int jbase = blockIdx.y * 128;

    for (int idx = tid; idx < 128 * K; idx += 128) {
        int r = idx / K, k = idx - r * K;
        float wv;
        if (DUAL) {
            wv = (k < 128) ? W[(size_t)(jbase + r) * wstride + k]
                           : W2[(size_t)(jbase + r) * wstride + (k - 128)];
        } else {
            wv = W[(size_t)(jbase + r) * wstride + k];
        }
        Ws[r * KP + k] = wv;
    }
    float b = (bias ? bias[jbase + tid] : 0.0f) + (bias2 ? bias2[jbase + tid] : 0.0f);

    const int stride = gridDim.x * NT;
    int t0 = blockIdx.x * NT;
    float4 pre[NPRE];
    if (t0 < n) {
        int lim = min(NT, n - t0) * KC4;
#pragma unroll
        for (int i = 0; i < NPRE; ++i) {
            int idx = tid + i * 128;
            if (idx < lim) {
                int row = idx / KC4, c4 = idx - row * KC4;
                float4 v = *(const float4*)(A + (size_t)(t0 + row) * astA + c4 * 4);
                if (A2) {
                    float4 v2 = *(const float4*)(A2 + (size_t)(t0 + row) * astA2 + c4 * 4);
                    v.x += v2.x; v.y += v2.y; v.z += v2.z; v.w += v2.w;
                }
                pre[i] = v;
            } else pre[i] = make_float4(0.f, 0.f, 0.f, 0.f);
        }
    }
    __syncthreads();

    const float4* wrow = (const float4*)(Ws + (size_t)tid * KP);

    for (; t0 < n; t0 += stride) {
        int cnt = min(NT, n - t0);
#pragma unroll
        for (int i = 0; i < NPRE; ++i)
            ((float4*)ins)[tid + i * 128] = pre[i];
        __syncthreads();
        int tn = t0 + stride;
        if (tn < n) {
            int lim = min(NT, n - tn) * KC4;
#pragma unroll
            for (int i = 0; i < NPRE; ++i) {
                int idx = tid + i * 128;
                if (idx < lim) {
                    int row = idx / KC4, c4 = idx - row * KC4;
                    float4 v = *(const float4*)(A + (size_t)(tn + row) * astA + c4 * 4);
                    if (A2) {
                        float4 v2 = *(const float4*)(A2 + (size_t)(tn + row) * astA2 + c4 * 4);
                        v.x += v2.x; v.y += v2.y; v.z += v2.z; v.w += v2.w;
                    }
                    pre[i] = v;
                } else pre[i] = make_float4(0.f, 0.f, 0.f, 0.f);
            }
        }
        float acc[NT];
#pragma unroll
        for (int q = 0; q < NT; ++q) acc[q] = 0.f;

        const float4* ins4 = (const float4*)ins;
#pragma unroll 4
        for (int k4 = 0; k4 < KC4; ++k4) {
            float4 w = wrow[k4];
#pragma unroll
            for (int q = 0; q < NT; ++q) {
                float4 v = ins4[q * KC4 + k4];
                acc[q] += w.x * v.x + w.y * v.y + w.z * v.z + w.w * v.w;
            }
        }
        for (int q = 0; q < cnt; ++q) {
            float r = acc[q] + b;
            if (ACT == 1) r = (r >= 0.f) ? r : 0.01f * r;
            else if (ACT == 2) r = fmaxf(r, 0.f);
            else if (ACT == 3) r = (r > 0.f) ? r : expm1f(r);
            out[(size_t)(t0 + q) * Jtotal + jbase + tid] = r;
        }
        __syncthreads();
    }
}

// ---------------- dense1m: J=128 GEMM on tensor cores (split-bf16) ---------
template <int ACT>
__global__ void __launch_bounds__(512, 2) dense1m_kernel(
    const float* __restrict__ A, const float* __restrict__ W,
    const float* __restrict__ bias, float* __restrict__ out,
    int n, int wstride)
{
    constexpr int KP2 = 136;
    constexpr int NT = 32;
    extern __shared__ __nv_bfloat16 smb[];
    __nv_bfloat16* Wh = smb;
    __nv_bfloat16* Wl = smb + 128 * KP2;
    __nv_bfloat16* Ah = smb + 2 * 128 * KP2;
    __nv_bfloat16* Al = Ah + NT * KP2;
    const int tid = threadIdx.x;
    const int lane = tid & 31, w = tid >> 5;
    const int wm = w >> 3, wg = w & 7;
    const int jb = wg * 16;

    for (int idx = tid; idx < 128 * 32; idx += 512) {
        int r = idx >> 5, c4 = idx & 31;
        float4 v = ((const float4*)(W + (size_t)r * wstride))[c4];
        bf16split4(v, (unsigned*)&Wh[r * KP2 + c4 * 4], (unsigned*)&Wl[r * KP2 + c4 * 4]);
    }

    const unsigned a_lane = (((lane & 15) * KP2) + (((lane >> 4) & 1) << 3)) * 2;
    const unsigned b_lane = ((((lane & 7) + (((lane >> 4) & 1) << 3)) * KP2)
                             + (((lane >> 3) & 1) << 3)) * 2;
    const unsigned sAh = (unsigned)__cvta_generic_to_shared(Ah) + a_lane + wm * 16 * KP2 * 2;
    const unsigned sAl = (unsigned)__cvta_generic_to_shared(Al) + a_lane + wm * 16 * KP2 * 2;
    const unsigned sWh = (unsigned)__cvta_generic_to_shared(Wh) + b_lane + (unsigned)jb * KP2 * 2;
    const unsigned sWl = (unsigned)__cvta_generic_to_shared(Wl) + b_lane + (unsigned)jb * KP2 * 2;

    __syncthreads();

    const int stride = gridDim.x * NT;
    for (int t0 = blockIdx.x * NT; t0 < n; t0 += stride) {
        int cnt = min(NT, n - t0);
        int lim4 = cnt * 32;
#pragma unroll
        for (int i = 0; i < 2; ++i) {
            int idx = tid + i * 512;
            float4 v = (idx < lim4) ? ((const float4*)(A + (size_t)t0 * 128))[idx]
                                    : make_float4(0.f, 0.f, 0.f, 0.f);
            int node = idx >> 5, kk = (idx & 31) << 2;
            bf16split4(v, (unsigned*)&Ah[node * KP2 + kk], (unsigned*)&Al[node * KP2 + kk]);
        }
        __syncthreads();

        float acc[2][4];
#pragma unroll
        for (int c = 0; c < 2; ++c)
#pragma unroll
            for (int e = 0; e < 4; ++e) acc[c][e] = 0.f;

#pragma unroll
        for (int ks = 0; ks < 8; ++ks) {
            const unsigned kb = ks * 32;
            unsigned ah[4], al[4], bh[4], bl[4];
            ldm4(ah, sAh + kb);
            ldm4(al, sAl + kb);
            ldm4(bh, sWh + kb);
            ldm4(bl, sWl + kb);
            mma16816(acc[0], ah, bh + 0);
            mma16816(acc[0], ah, bl + 0);
            mma16816(acc[0], al, bh + 0);
            mma16816(acc[1], ah, bh + 2);
            mma16816(acc[1], ah, bl + 2);
            mma16816(acc[1], al, bh + 2);
        }

        const int rbase = wm * 16 + (lane >> 2);
        const int colb = (lane & 3) * 2;
#pragma unroll
        for (int half = 0; half < 2; ++half) {
            int rl = rbase + half * 8;
            if (rl < cnt) {
                size_t node = (size_t)(t0 + rl);
#pragma unroll
                for (int sub = 0; sub < 2; ++sub) {
                    int j = jb + sub * 8 + colb;
                    float2 res;
#pragma unroll
                    for (int e = 0; e < 2; ++e) {
                        float r = acc[sub][half * 2 + e] + (bias ? __ldg(&bias[j + e]) : 0.f);
                        if (ACT == 1) r = (r >= 0.f) ? r : 0.01f * r;
                        else if (ACT == 2) r = fmaxf(r, 0.f);
                        else if (ACT == 3) r = (r > 0.f) ? r : expm1f(r);
                        if (e == 0) res.x = r; else res.y = r;
                    }
                    *(float2*)&out[node * 128 + j] = res;
                }
            }
        }
        __syncthreads();
    }
}

// ---------------- dense3m: GRU-gate GEMM on tensor cores (split-bf16) ------
template <int EPI>
__global__ void __launch_bounds__(512) dense3m_kernel(
    const float* __restrict__ A, const float* __restrict__ W,
    const float* __restrict__ bias, float* __restrict__ out,
    const float* __restrict__ gi, int n)
{
    constexpr int KP2 = 136;
    constexpr int NT = 32;
    extern __shared__ __nv_bfloat16 smb[];
    __nv_bfloat16* Wh = smb;
    __nv_bfloat16* Wl = smb + 384 * KP2;
    __nv_bfloat16* Ah = smb + 2 * 384 * KP2;
    __nv_bfloat16* Al = Ah + NT * KP2;
    const int tid = threadIdx.x;
    const int lane = tid & 31, w = tid >> 5;
    const int wm = w >> 3, wg = w & 7;
    const int jb = wg * 16;

    for (int idx = tid; idx < 384 * 32; idx += 512) {
        float4 v = ((const float4*)W)[idx];
        int r = idx >> 5, kk = (idx & 31) << 2;
        bf16split4(v, (unsigned*)&Wh[r * KP2 + kk], (unsigned*)&Wl[r * KP2 + kk]);
    }

    const unsigned a_lane = (((lane & 15) * KP2) + (((lane >> 4) & 1) << 3)) * 2;
    const unsigned b_lane = ((((lane & 7) + (((lane >> 4) & 1) << 3)) * KP2)
                             + (((lane >> 3) & 1) << 3)) * 2;
    const unsigned sAh = (unsigned)__cvta_generic_to_shared(Ah) + a_lane + wm * 16 * KP2 * 2;
    const unsigned sAl = (unsigned)__cvta_generic_to_shared(Al) + a_lane + wm * 16 * KP2 * 2;
    const unsigned sWh = (unsigned)__cvta_generic_to_shared(Wh) + b_lane;
    const unsigned sWl = (unsigned)__cvta_generic_to_shared(Wl) + b_lane;

    __syncthreads();

    const int stride = gridDim.x * NT;
    for (int t0 = blockIdx.x * NT; t0 < n; t0 += stride) {
        int cnt = min(NT, n - t0);
        int lim4 = cnt * 32;
#pragma unroll
        for (int i = 0; i < 2; ++i) {
            int idx = tid + i * 512;
            float4 v = (idx < lim4) ? ((const float4*)(A + (size_t)t0 * 128))[idx]
                                    : make_float4(0.f, 0.f, 0.f, 0.f);
            int node = idx >> 5, kk = (idx & 31) << 2;
            bf16split4(v, (unsigned*)&Ah[node * KP2 + kk], (unsigned*)&Al[node * KP2 + kk]);
        }
        __syncthreads();

        float acc[6][4];
#pragma unroll
        for (int c = 0; c < 6; ++c)
#pragma unroll
            for (int e = 0; e < 4; ++e) acc[c][e] = 0.f;

#pragma unroll
        for (int ks = 0; ks < 8; ++ks) {
            const unsigned kb = ks * 32;
            unsigned ah[4], al[4];
            ldm4(ah, sAh + kb);
            ldm4(al, sAl + kb);
#pragma unroll
            for (int pb = 0; pb < 3; ++pb) {
                const unsigned nb = (unsigned)(jb + pb * 128) * KP2 * 2 + kb;
                unsigned bh[4], bl[4];
                ldm4(bh, sWh + nb);
                ldm4(bl, sWl + nb);
                mma16816(acc[pb * 2 + 0], ah, bh + 0);
                mma16816(acc[pb * 2 + 0], ah, bl + 0);
                mma16816(acc[pb * 2 + 0], al, bh + 0);
                mma16816(acc[pb * 2 + 1], ah, bh + 2);
                mma16816(acc[pb * 2 + 1], ah, bl + 2);
                mma16816(acc[pb * 2 + 1], al, bh + 2);
            }
        }

        const int rbase = wm * 16 + (lane >> 2);
        const int colb = (lane & 3) * 2;
#pragma unroll
        for (int half = 0; half < 2; ++half) {
            int rl = rbase + half * 8;
            if (rl < cnt) {
                size_t node = (size_t)(t0 + rl);
                if (EPI == 0) {
#pragma unroll
                    for (int pb = 0; pb < 3; ++pb)
#pragma unroll
                        for (int sub = 0; sub < 2; ++sub) {
                            int gate = jb + pb * 128 + sub * 8 + colb;
                            float2 v;
                            v.x = acc[pb * 2 + sub][half * 2 + 0] + __ldg(&bias[gate]);
                            v.y = acc[pb * 2 + sub][half * 2 + 1] + __ldg(&bias[gate + 1]);
                            *(float2*)&out[node * 384 + gate] = v;
                        }
                } else {
#pragma unroll
                    for (int sub = 0; sub < 2; ++sub) {
                        int j = jb + sub * 8 + colb;
                        float2 res;
#pragma unroll
                        for (int e = 0; e < 2; ++e) {
                            int je = j + e;
                            float hr = acc[sub][half * 2 + e] + __ldg(&bias[je]);
                            float hz = acc[2 + sub][half * 2 + e] + __ldg(&bias[128 + je]);
                            float hn = acc[4 + sub][half * 2 + e] + __ldg(&bias[256 + je]);
                            float r = sigm(gi[node * 384 + je] + hr);
                            float z = sigm(gi[node * 384 + 128 + je] + hz);
                            float nn = tanhf(gi[node * 384 + 256 + je] + r * hn);
                            float hv = A[node * 128 + je];
                            float o = fmaxf((1.f - z) * nn + z * hv, 0.f);
                            if (e == 0) res.x = o; else res.y = o;
                        }
                        *(float2*)&out[node * 128 + j] = res;
                    }
                }
            }
        }
        __syncthreads();
    }
}

// ---------------- nd gather (CSR, depth-2, static registers) ----------------
__global__ void __launch_bounds__(256) nd_gather_kernel(
    const float* __restrict__ p, const float* __restrict__ ea,
    const int* __restrict__ src, const int* __restrict__ off,
    const int* __restrict__ eid, const float* __restrict__ w1,
    float* __restrict__ tsum)
{
    __shared__ float W1b[16 * 128];
    const int tid = threadIdx.x;
    for (int idx = tid; idx < 16 * 128; idx += 256) {
        int k = idx >> 7, j = idx & 127;
        W1b[idx] = w1[j * 144 + 128 + k];
    }
    __syncthreads();
    int n = blockIdx.x * 8 + (tid >> 5);
    if (n >= NN) return;
    int lane = tid & 31;
    int beg = off[n], end = off[n + 1];
    float4 acc = make_float4(0.f, 0.f, 0.f, 0.f);
    const float4* W1b4 = (const float4*)W1b;
    const float4* p4 = (const float4*)p;

    float4 v0, v1;
    float ea0 = 0.f, ea1 = 0.f;
    if (beg < end) {
        int ed = __ldg(&eid[beg]);
        int s = __ldg(&src[ed]);
        ea0 = (lane < 16) ? __ldg(&ea[(size_t)ed * 16 + lane]) : 0.f;
        v0 = __ldg(&p4[(size_t)s * 32 + lane]);
    }
    if (beg + 1 < end) {
        int ed = __ldg(&eid[beg + 1]);
        int s = __ldg(&src[ed]);
        ea1 = (lane < 16) ? __ldg(&ea[(size_t)ed * 16 + lane]) : 0.f;
        v1 = __ldg(&p4[(size_t)s * 32 + lane]);
    }
    int e = beg;
    for (; e + 1 < end; e += 2) {
        float4 tA = v0; float eA = ea0;
        float4 tB = v1; float eB = ea1;
        if (e + 2 < end) {
            int ed = __ldg(&eid[e + 2]);
            int s = __ldg(&src[ed]);
            ea0 = (lane < 16) ? __ldg(&ea[(size_t)ed * 16 + lane]) : 0.f;
            v0 = __ldg(&p4[(size_t)s * 32 + lane]);
        }
        if (e + 3 < end) {
            int ed = __ldg(&eid[e + 3]);
            int s = __ldg(&src[ed]);
            ea1 = (lane < 16) ? __ldg(&ea[(size_t)ed * 16 + lane]) : 0.f;
            v1 = __ldg(&p4[(size_t)s * 32 + lane]);
        }
#pragma unroll
        for (int k = 0; k < 16; ++k) {
            float ek = __shfl_sync(0xFFFFFFFFu, eA, k);
            float4 w = W1b4[k * 32 + lane];
            tA.x += ek * w.x; tA.y += ek * w.y; tA.z += ek * w.z; tA.w += ek * w.w;
        }
        tA.x = (tA.x >= 0.f) ? tA.x : 0.01f * tA.x;
        tA.y = (tA.y >= 0.f) ? tA.y : 0.01f * tA.y;
        tA.z = (tA.z >= 0.f) ? tA.z : 0.01f * tA.z;
        tA.w = (tA.w >= 0.f) ? tA.w : 0.01f * tA.w;
        acc.x += tA.x; acc.y += tA.y; acc.z += tA.z; acc.w += tA.w;
#pragma unroll
        for (int k = 0; k < 16; ++k) {
            float ek = __shfl_sync(0xFFFFFFFFu, eB, k);
            float4 w = W1b4[k * 32 + lane];
            tB.x += ek * w.x; tB.y += ek * w.y; tB.z += ek * w.z; tB.w += ek * w.w;
        }
        tB.x = (tB.x >= 0.f) ? tB.x : 0.01f * tB.x;
        tB.y = (tB.y >= 0.f) ? tB.y : 0.01f * tB.y;
        tB.z = (tB.z >= 0.f) ? tB.z : 0.01f * tB.z;
        tB.w = (tB.w >= 0.f) ? tB.w : 0.01f * tB.w;
        acc.x += tB.x; acc.y += tB.y; acc.z += tB.z; acc.w += tB.w;
    }
    if (e < end) {
        float4 tA = v0; float eA = ea0;
#pragma unroll
        for (int k = 0; k < 16; ++k) {
            float ek = __shfl_sync(0xFFFFFFFFu, eA, k);
            float4 w = W1b4[k * 32 + lane];
            tA.x += ek * w.x; tA.y += ek * w.y; tA.z += ek * w.z; tA.w += ek * w.w;
        }
        tA.x = (tA.x >= 0.f) ? tA.x : 0.01f * tA.x;
        tA.y = (tA.y >= 0.f) ? tA.y : 0.01f * tA.y;
        tA.z = (tA.z >= 0.f) ? tA.z : 0.01f * tA.z;
        tA.w = (tA.w >= 0.f) ? tA.w : 0.01f * tA.w;
        acc.x += tA.x; acc.y += tA.y; acc.z += tA.z; acc.w += tA.w;
    }
    ((float4*)tsum)[(size_t)n * 32 + lane] = acc;
}

// ---------------- GAT attention dots ----------------
__global__ void attn_dots_kernel(const float* __restrict__ xp, const float* __restrict__ asrc,
                                 const float* __restrict__ adst, float* __restrict__ as_,
                                 float* __restrict__ ad_) {
    int n = (blockIdx.x * blockDim.x + threadIdx.x) >> 5;
    int lane = threadIdx.x & 31;
    if (n >= NN) return;
    float4 v = ((const float4*)xp)[(size_t)n * 32 + lane];
    float4 w1 = ((const float4*)asrc)[lane];
    float4 w2 = ((const float4*)adst)[lane];
    float sa = v.x * w1.x + v.y * w1.y + v.z * w1.z + v.w * w1.w;
    float sd = v.x * w2.x + v.y * w2.y + v.z * w2.z + v.w * w2.w;
#pragma unroll
    for (int o = 16; o; o >>= 1) {
        sa += __shfl_xor_sync(0xFFFFFFFFu, sa, o);
        sd += __shfl_xor_sync(0xFFFFFFFFu, sd, o);
    }
    if (lane == 0) { as_[n] = sa; ad_[n] = sd; }
}

// ---------------- GAT gather (CSR, online softmax, depth-2 static) ---------
__global__ void __launch_bounds__(256) gat_gather_kernel(
    const int* __restrict__ src, const int* __restrict__ off, const int* __restrict__ eid,
    const float* __restrict__ as_, const float* __restrict__ ad_,
    const float* __restrict__ xp, const float* __restrict__ bias,
    float* __restrict__ hout)
{
    int n = blockIdx.x * 8 + (threadIdx.x >> 5);
    if (n >= NN) return;
    int lane = threadIdx.x & 31;
    int beg = off[n], end = off[n + 1];
    float adn = ad_[n];
    float m = -INFINITY, den = 0.f;
    float4 acc = make_float4(0.f, 0.f, 0.f, 0.f);
    const float4* xp4 = (const float4*)xp;

    float4 v0, v1;
    float av0 = 0.f, av1 = 0.f;
    if (beg < end) {
        int s = __ldg(&src[__ldg(&eid[beg])]);
        av0 = __ldg(&as_[s]);
        v0 = __ldg(&xp4[(size_t)s * 32 + lane]);
    }
    if (beg + 1 < end) {
        int s = __ldg(&src[__ldg(&eid[beg + 1])]);
        av1 = __ldg(&as_[s]);
        v1 = __ldg(&xp4[(size_t)s * 32 + lane]);
    }
    int e = beg;
    for (; e + 1 < end; e += 2) {
        float aA = av0 + adn; float4 vA = v0;
        float aB = av1 + adn; float4 vB = v1;
        if (e + 2 < end) {
            int s = __ldg(&src[__ldg(&eid[e + 2])]);
            av0 = __ldg(&as_[s]);
            v0 = __ldg(&xp4[(size_t)s * 32 + lane]);
        }
        if (e + 3 < end) {
            int s = __ldg(&src[__ldg(&eid[e + 3])]);
            av1 = __ldg(&as_[s]);
            v1 = __ldg(&xp4[(size_t)s * 32 + lane]);
        }
        aA = (aA >= 0.f) ? aA : 0.01f * aA;
        if (aA > m) {
            float f = __expf(m - aA);
            den *= f;
            acc.x *= f; acc.y *= f; acc.z *= f; acc.w *= f;
            m = aA;
        }
        {
            float wv = __expf(aA - m);
            den += wv;
            acc.x += wv * vA.x; acc.y += wv * vA.y; acc.z += wv * vA.z; acc.w += wv * vA.w;
        }
        aB = (aB >= 0.f) ? aB : 0.01f * aB;
        if (aB > m) {
            float f = __expf(m - aB);
            den *= f;
            acc.x *= f; acc.y *= f; acc.z *= f; acc.w *= f;
            m = aB;
        }
        {
            float wv = __expf(aB - m);
            den += wv;
            acc.x += wv * vB.x; acc.y += wv * vB.y; acc.z += wv * vB.z; acc.w += wv * vB.w;
        }
    }
    if (e < end) {
        float aA = av0 + adn; float4 vA = v0;
        aA = (aA >= 0.f) ? aA : 0.01f * aA;
        if (aA > m) {
            float f = __expf(m - aA);
            den *= f;
            acc.x *= f; acc.y *= f; acc.z *= f; acc.w *= f;
            m = aA;
        }
        float wv = __expf(aA - m);
        den += wv;
        acc.x += wv * vA.x; acc.y += wv * vA.y; acc.z += wv * vA.z; acc.w += wv * vA.w;
    }
    float inv = (den > 0.f) ? 1.f / den : 0.f;
    float4 b = ((const float4*)bias)[lane];
    float4 r;
    r.x = acc.x * inv + b.x; r.y = acc.y * inv + b.y;
    r.z = acc.z * inv + b.z; r.w = acc.w * inv + b.w;
    r.x = (r.x > 0.f) ? r.x : expm1f(r.x);
    r.y = (r.y > 0.f) ? r.y : expm1f(r.y);
    r.z = (r.z > 0.f) ? r.z : expm1f(r.z);
    r.w = (r.w > 0.f) ? r.w : expm1f(r.w);
    ((float4*)hout)[(size_t)n * 32 + lane] = r;
}

// ---------------- readout ----------------
__global__ void __launch_bounds__(128) graph_agg_kernel(const float* __restrict__ xcur,
                                                        const int* __restrict__ batch,
                                                        float* __restrict__ agg,
                                                        float* __restrict__ buf) {
    int g = blockIdx.x;
    int lo, hi;
    {
        int l = 0, r = NN;
        while (l < r) { int m = (l + r) >> 1; if (batch[m] < g) l = m + 1; else r = m; }
        lo = l;
    }
    {
        int l = lo, r = NN;
        while (l < r) { int m = (l + r) >> 1; if (batch[m] < g + 1) l = m + 1; else r = m; }
        hi = l;
    }
    float s = 0.f;
    for (int n = lo; n < hi; ++n) s += xcur[(size_t)n * 128 + threadIdx.x];
    agg[g * 128 + threadIdx.x] = s;
    buf[(size_t)g * 256 + threadIdx.x] = fmaxf(s, 0.f);
}

__global__ void lstm_combine_kernel(const float* __restrict__ gi, float* __restrict__ buf) {
    int t = blockIdx.x * blockDim.x + threadIdx.x;
    if (t >= NG * 128) return;
    int g = t >> 7, j = t & 127;
    size_t base = (size_t)g * 512;
    float gI = gi[base + j];
    float gF = gi[base + 128 + j];
    float gG = gi[base + 256 + j];
    float gO = gi[base + 384 + j];
    float c = buf[(size_t)g * 256 + 128 + j];
    float c2 = sigm(gF) * c + sigm(gI) * tanhf(gG);
    buf[(size_t)g * 256 + j] = sigm(gO) * tanhf(c2);
}

__global__ void final_kernel(const float* __restrict__ buf, const float* __restrict__ w,
                             const float* __restrict__ b, float* __restrict__ res) {
    int g = (blockIdx.x * blockDim.x + threadIdx.x) >> 5;
    int lane = threadIdx.x & 31;
    if (g >= NG) return;
    float4 v = ((const float4*)(buf + (size_t)g * 256))[lane];
    float4 ww = ((const float4*)w)[lane];
    float s = v.x * ww.x + v.y * ww.y + v.z * ww.z + v.w * ww.w;
#pragma unroll
    for (int o = 16; o; o >>= 1) s += __shfl_xor_sync(0xFFFFFFFFu, s, o);
    if (lane == 0) res[g] = s + b[0];
}

// ---------------- host ----------------
#define SM_J1K64  ((128 * 68 + 16 * 64) * 4)
#define SM_J1K128 ((128 * 132 + 16 * 128) * 4)
#define SM_J1K256 ((128 * 260 + 16 * 256) * 4)
#define SM_M1     ((2 * 128 * 136 + 2 * 32 * 136) * 2)
#define SM_M3     ((2 * 384 * 136 + 2 * 32 * 136) * 2)

extern "C" void kernel_launch(void* const* d_in, const int* in_sizes, int n_in,
                              void* d_out, int out_size) {
    const float* x        = (const float*)d_in[0];
    const int*   ei       = (const int*)  d_in[1];
    const float* ea       = (const float*)d_in[2];
    const int*   batch    = (const int*)  d_in[3];
    const float* lin1_w   = (const float*)d_in[4];
    const float* lin1_b   = (const float*)d_in[5];
    const float* nd_lin1w = (const float*)d_in[6];
    const float* nd_lin2w = (const float*)d_in[7];
    const float* nd_bias  = (const float*)d_in[8];
    const float* gru0_wih = (const float*)d_in[9];
    const float* gru0_whh = (const float*)d_in[10];
    const float* gru0_bih = (const float*)d_in[11];
    const float* gru0_bhh = (const float*)d_in[12];
    const float* gat_w    = (const float*)d_in[13];
    const float* gat_asrc = (const float*)d_in[14];
    const float* gat_adst = (const float*)d_in[15];
    const float* gat_b    = (const float*)d_in[16];
    const float* gru_wih  = (const float*)d_in[17];
    const float* gru_whh  = (const float*)d_in[18];
    const float* gru_bih  = (const float*)d_in[19];
    const float* gru_bhh  = (const float*)d_in[20];
    const float* gin_w    = (const float*)d_in[21];
    const float* gin_b    = (const float*)d_in[22];
    const float* lstm_wih = (const float*)d_in[23];
    const float* lstm_whh = (const float*)d_in[24];
    const float* lstm_bih = (const float*)d_in[25];
    const float* lstm_bhh = (const float*)d_in[26];
    const float* lin2_w   = (const float*)d_in[27];
    const float* lin2_b   = (const float*)d_in[28];
    float* out = (float*)d_out;

    const int* src = ei;
    const int* dst = ei + NE;

    float *px1, *pp, *ph, *pxc, *pgi, *pas, *pad;
    float *pagg, *pbuf, *pggi;
    int *pcnt, *poff, *ppos, *peid, *ppart;
    cudaGetSymbolAddress((void**)&px1, f_x1);
    cudaGetSymbolAddress((void**)&pp, f_p);
    cudaGetSymbolAddress((void**)&ph, f_h);
    cudaGetSymbolAddress((void**)&pxc, f_xcur);
    cudaGetSymbolAddress((void**)&pgi, f_gi);
    cudaGetSymbolAddress((void**)&pas, f_as);
    cudaGetSymbolAddress((void**)&pad, f_ad);
    cudaGetSymbolAddress((void**)&pagg, g_agg);
    cudaGetSymbolAddress((void**)&pbuf, g_buf);
    cudaGetSymbolAddress((void**)&pggi, g_gi);
    cudaGetSymbolAddress((void**)&pcnt, c_cnt);
    cudaGetSymbolAddress((void**)&poff, c_off);
    cudaGetSymbolAddress((void**)&ppos, c_pos);
    cudaGetSymbolAddress((void**)&peid, c_eid);
    cudaGetSymbolAddress((void**)&ppart, c_part);

    cudaFuncSetAttribute((const void*)dense_kernel<64, 1, 0>, cudaFuncAttributeMaxDynamicSharedMemorySize, SM_J1K64);
    cudaFuncSetAttribute((const void*)dense_kernel<128, 3, 0>, cudaFuncAttributeMaxDynamicSharedMemorySize, SM_J1K128);
    cudaFuncSetAttribute((const void*)dense_kernel<256, 0, 1>, cudaFuncAttributeMaxDynamicSharedMemorySize, SM_J1K256);
    cudaFuncSetAttribute((const void*)dense1m_kernel<0>, cudaFuncAttributeMaxDynamicSharedMemorySize, SM_M1);
    cudaFuncSetAttribute((const void*)dense1m_kernel<3>, cudaFuncAttributeMaxDynamicSharedMemorySize, SM_M1);
    cudaFuncSetAttribute((const void*)dense3m_kernel<0>, cudaFuncAttributeMaxDynamicSharedMemorySize, SM_M3);
    cudaFuncSetAttribute((const void*)dense3m_kernel<1>, cudaFuncAttributeMaxDynamicSharedMemorySize, SM_M3);

    const int GP1b = 592;
    const int GPD1 = 296;
    const int GP3 = 148;
    const int NPART = (NN + 1023) / 1024;
    const int tilesG = (NG + 15) / 16;
    const int ZB = 256;

    // 0) x1 = leaky(x @ lin1_w.T + b)
    dense_kernel<64, 1, 0><<<dim3(GP1b, 1), 128, SM_J1K64>>>(
        x, nullptr, lin1_w, nullptr, lin1_b, nullptr, px1, NN, 128, 64, 64, 0);
    // 1-2) CSR phase A
    zero_i_kernel<<<(NN + ZB - 1) / ZB, ZB>>>(pcnt, NN);
    hist_kernel<<<(NE + ZB - 1) / ZB, ZB>>>(dst, pcnt);
    // 3) p = x1 @ W1a.T   <-- PROFILED
    dense1m_kernel<0><<<GPD1, 512, SM_M1>>>(px1, nd_lin1w, nullptr, pp, NN, 144);
    // 4-7) CSR phase B
    scan_part_kernel<<<NPART, 256>>>(pcnt, ppart);
    scan_mid_kernel<<<1, 32>>>(ppart, NPART);
    scan_final_kernel<<<NPART, 256>>>(pcnt, ppart, poff, ppos);
    fill_kernel<<<(NE + ZB - 1) / ZB, ZB>>>(dst, ppos, peid);
    // tsum
    nd_gather_kernel<<<(NN + 7) / 8, 256>>>(pp, ea, src, poff, peid, nd_lin1w, pgi);
    // h = elu(tsum @ W2.T + nd_bias)
    dense1m_kernel<3><<<GPD1, 512, SM_M1>>>(pgi, nd_lin2w, nd_bias, ph, NN, 128);
    // GRU0
    dense3m_kernel<0><<<GP3, 512, SM_M3>>>(ph, gru0_wih, gru0_bih, pgi, nullptr, NN);
    dense3m_kernel<1><<<GP3, 512, SM_M3>>>(px1, gru0_whh, gru0_bhh, pxc, pgi, NN);

    // GAT layers
    for (int l = 0; l < 2; ++l) {
        dense1m_kernel<0><<<GPD1, 512, SM_M1>>>(pxc, gat_w + (size_t)l * 128 * 128, nullptr, pp, NN, 128);
        attn_dots_kernel<<<(NN * 32 + ZB - 1) / ZB, ZB>>>(pp, gat_asrc + l * 128, gat_adst + l * 128, pas, pad);
        gat_gather_kernel<<<(NN + 7) / 8, 256>>>(src, poff, peid, pas, pad, pp, gat_b + l * 128, ph);
        dense3m_kernel<0><<<GP3, 512, SM_M3>>>(ph, gru_wih + (size_t)l * 384 * 128, gru_bih + l * 384, pgi, nullptr, NN);
        dense3m_kernel<1><<<GP3, 512, SM_M3>>>(pxc, gru_whh + (size_t)l * 384 * 128, gru_bhh + l * 384, pxc, pgi, NN);
    }

    // readout (streamlined: 8 launches)
    graph_agg_kernel<<<NG, 128>>>(pxc, batch, pagg, pbuf);
    for (int t = 0; t < 2; ++t) {
        // hh = elu(gin_w @ (out + agg) + gin_b), written to buf[:,128:256]
        dense_kernel<128, 3, 0><<<dim3(tilesG, 1), 128, SM_J1K128>>>(
            pbuf, pagg, gin_w, nullptr, gin_b, nullptr, pbuf + 128, NG, 256, 128, 256, 128);
        // gates = [out|hh] @ [wih|whh].T + (bih + bhh)   (K=256 dual-weight)
        dense_kernel<256, 0, 1><<<dim3(tilesG, 4), 128, SM_J1K256>>>(
            pbuf, nullptr, lstm_wih, lstm_whh, lstm_bih, lstm_bhh, pggi, NG, 512, 128, 256, 0);
        lstm_combine_kernel<<<(NG * 128 + ZB - 1) / ZB, ZB>>>(pggi, pbuf);
    }
    final_kernel<<<(NG * 32 + 127) / 128, 128>>>(pbuf, lin2_w, lin2_b, out);
}

// round 16
// speedup vs baseline: 1.0890x; 1.0890x over previous
#include <cuda_runtime.h>
#include <cuda_bf16.h>
#include <math.h>

#define NN 50000
#define NE 500000
#define NG 2000

typedef unsigned long long u64t;

// ---------------- scratch (device globals) ----------------
__device__ float f_x1  [NN * 128];
__device__ float f_p   [NN * 128];
__device__ float f_h   [NN * 128];
__device__ float f_xcur[NN * 128];
__device__ float f_gi  [NN * 3 * 128];
__device__ float f_as  [NN];
__device__ float f_ad  [NN];
__device__ float g_agg [NG * 128];
__device__ float g_out [NG * 128];
__device__ float g_hh  [NG * 128];
__device__ float g_tmp [NG * 128];
__device__ float g_gi  [NG * 4 * 128];
__device__ float g_gh  [NG * 4 * 128];
__device__ int c_cnt[NN];
__device__ int c_off[NN + 1];
__device__ int c_pos[NN];
__device__ int c_eid[NE];
__device__ int c_part[64];

__device__ __forceinline__ float sigm(float x) { return 1.0f / (1.0f + expf(-x)); }

__device__ __forceinline__ void ldm4(unsigned* r, unsigned addr) {
    asm volatile("ldmatrix.sync.aligned.m8n8.x4.shared.b16 {%0,%1,%2,%3}, [%4];"
        : "=r"(r[0]), "=r"(r[1]), "=r"(r[2]), "=r"(r[3]) : "r"(addr));
}
__device__ __forceinline__ void mma16816(float* c, const unsigned* a, const unsigned* b) {
    asm volatile("mma.sync.aligned.m16n8k16.row.col.f32.bf16.bf16.f32 "
        "{%0,%1,%2,%3}, {%4,%5,%6,%7}, {%8,%9}, {%0,%1,%2,%3};"
        : "+f"(c[0]), "+f"(c[1]), "+f"(c[2]), "+f"(c[3])
        : "r"(a[0]), "r"(a[1]), "r"(a[2]), "r"(a[3]), "r"(b[0]), "r"(b[1]));
}
__device__ __forceinline__ void bf16split4(float4 v, unsigned* ph_, unsigned* pl_) {
    __nv_bfloat16 h0 = __float2bfloat16(v.x), h1 = __float2bfloat16(v.y);
    __nv_bfloat16 h2 = __float2bfloat16(v.z), h3 = __float2bfloat16(v.w);
    __nv_bfloat16 l0 = __float2bfloat16(v.x - __bfloat162float(h0));
    __nv_bfloat16 l1 = __float2bfloat16(v.y - __bfloat162float(h1));
    __nv_bfloat16 l2 = __float2bfloat16(v.z - __bfloat162float(h2));
    __nv_bfloat16 l3 = __float2bfloat16(v.w - __bfloat162float(h3));
    __nv_bfloat162 hA, hB, lA, lB;
    hA.x = h0; hA.y = h1; hB.x = h2; hB.y = h3;
    lA.x = l0; lA.y = l1; lB.x = l2; lB.y = l3;
    ph_[0] = *(unsigned*)&hA; ph_[1] = *(unsigned*)&hB;
    pl_[0] = *(unsigned*)&lA; pl_[1] = *(unsigned*)&lB;
}

// ---------------- CSR build ----------------
__global__ void zero_i_kernel(int* p, int n) {
    int t = blockIdx.x * blockDim.x + threadIdx.x;
    if (t < n) p[t] = 0;
}
__global__ void hist_kernel(const int* __restrict__ dst, int* __restrict__ cnt) {
    int e = blockIdx.x * blockDim.x + threadIdx.x;
    if (e < NE) atomicAdd(&cnt[dst[e]], 1);
}
__global__ void __launch_bounds__(256) scan_part_kernel(const int* __restrict__ cnt,
                                                        int* __restrict__ part) {
    __shared__ int sm[256];
    int base = blockIdx.x * 1024;
    int s = 0;
    for (int i = threadIdx.x; i < 1024; i += 256) {
        int idx = base + i;
        s += (idx < NN) ? cnt[idx] : 0;
    }
    sm[threadIdx.x] = s;
    __syncthreads();
    for (int d = 128; d; d >>= 1) {
        if (threadIdx.x < d) sm[threadIdx.x] += sm[threadIdx.x + d];
        __syncthreads();
    }
    if (threadIdx.x == 0) part[blockIdx.x] = sm[0];
}
__global__ void scan_mid_kernel(int* part, int npart) {
    if (threadIdx.x == 0) {
        int run = 0;
        for (int i = 0; i < npart; ++i) { int v = part[i]; part[i] = run; run += v; }
    }
}
__global__ void __launch_bounds__(256) scan_final_kernel(const int* __restrict__ cnt,
                                                         const int* __restrict__ part,
                                                         int* __restrict__ off,
                                                         int* __restrict__ pos) {
    __shared__ int wsum[8];
    int base = blockIdx.x * 1024;
    int lane = threadIdx.x & 31, wid = threadIdx.x >> 5;
    int v[4]; int s = 0;
    int i0 = base + threadIdx.x * 4;
#pragma unroll
    for (int i = 0; i < 4; ++i) {
        int idx = i0 + i;
        v[i] = (idx < NN) ? cnt[idx] : 0;
        s += v[i];
    }
    int ps = s;
#pragma unroll
    for (int o = 1; o < 32; o <<= 1) {
        int t = __shfl_up_sync(0xFFFFFFFFu, ps, o);
        if (lane >= o) ps += t;
    }
    if (lane == 31) wsum[wid] = ps;
    __syncthreads();
    if (threadIdx.x == 0) {
        int run = 0;
#pragma unroll
        for (int w = 0; w < 8; ++w) { int t = wsum[w]; wsum[w] = run; run += t; }
    }
    __syncthreads();
    int excl = ps - s + wsum[wid] + part[blockIdx.x];
#pragma unroll
    for (int i = 0; i < 4; ++i) {
        int idx = i0 + i;
        if (idx < NN) { off[idx] = excl; pos[idx] = excl; }
        excl += v[i];
    }
    if (blockIdx.x == 0 && threadIdx.x == 0) off[NN] = NE;
}
__global__ void fill_kernel(const int* __restrict__ dst, int* __restrict__ pos,
                            int* __restrict__ eid) {
    int e = blockIdx.x * blockDim.x + threadIdx.x;
    if (e < NE) {
        int idx = atomicAdd(&pos[dst[e]], 1);
        eid[idx] = e;
    }
}

// ---------------- dense GEMM JPT=1 generic (K=64 + graph-level) -----------
template <int K, int ACT>
__global__ void __launch_bounds__(128) dense_kernel(
    const float* __restrict__ A, const float* __restrict__ W,
    const float* __restrict__ bias, float* __restrict__ out,
    int n, int Jtotal, int wstride)
{
    constexpr int KP = K + 4;
    constexpr int NT = 16;
    constexpr int NPRE = NT * K / 512;
    extern __shared__ float sm[];
    float* Ws  = sm;
    float* ins = sm + 128 * KP;
    const int tid = threadIdx.x;
    const int jbase = blockIdx.y * 128;

    for (int idx = tid; idx < 128 * K; idx += 128) {
        int r = idx / K, k = idx - r * K;
        Ws[r * KP + k] = W[(size_t)(jbase + r) * wstride + k];
    }
    float b = bias ? bias[jbase + tid] : 0.0f;

    const int stride = gridDim.x * NT;
    int t0 = blockIdx.x * NT;
    float4 pre[NPRE];
    if (t0 < n) {
        int lim = min(NT, n - t0) * (K / 4);
#pragma unroll
        for (int i = 0; i < NPRE; ++i) {
            int idx = tid + i * 128;
            pre[i] = (idx < lim) ? ((const float4*)(A + (size_t)t0 * K))[idx]
                                 : make_float4(0.f, 0.f, 0.f, 0.f);
        }
    }
    __syncthreads();

    const float4* wrow = (const float4*)(Ws + (size_t)tid * KP);

    for (; t0 < n; t0 += stride) {
        int cnt = min(NT, n - t0);
#pragma unroll
        for (int i = 0; i < NPRE; ++i)
            ((float4*)ins)[tid + i * 128] = pre[i];
        __syncthreads();
        int tn = t0 + stride;
        if (tn < n) {
            int lim = min(NT, n - tn) * (K / 4);
#pragma unroll
            for (int i = 0; i < NPRE; ++i) {
                int idx = tid + i * 128;
                pre[i] = (idx < lim) ? ((const float4*)(A + (size_t)tn * K))[idx]
                                     : make_float4(0.f, 0.f, 0.f, 0.f);
            }
        }
        float acc[NT];
#pragma unroll
        for (int q = 0; q < NT; ++q) acc[q] = 0.f;

        const float4* ins4 = (const float4*)ins;
#pragma unroll 4
        for (int k4 = 0; k4 < K / 4; ++k4) {
            float4 w = wrow[k4];
#pragma unroll
            for (int q = 0; q < NT; ++q) {
                float4 v = ins4[q * (K / 4) + k4];
                acc[q] += w.x * v.x + w.y * v.y + w.z * v.z + w.w * v.w;
            }
        }
        for (int q = 0; q < cnt; ++q) {
            float r = acc[q] + b;
            if (ACT == 1) r = (r >= 0.f) ? r : 0.01f * r;
            else if (ACT == 2) r = fmaxf(r, 0.f);
            else if (ACT == 3) r = (r > 0.f) ? r : expm1f(r);
            out[(size_t)(t0 + q) * Jtotal + jbase + tid] = r;
        }
        __syncthreads();
    }
}

// ---------------- dense1m: J=128 GEMM on tensor cores (split-bf16, prefetch)
template <int ACT>
__global__ void __launch_bounds__(512, 2) dense1m_kernel(
    const float* __restrict__ A, const float* __restrict__ W,
    const float* __restrict__ bias, float* __restrict__ out,
    int n, int wstride)
{
    constexpr int KP2 = 136;
    constexpr int NT = 32;
    extern __shared__ __nv_bfloat16 smb[];
    __nv_bfloat16* Wh = smb;
    __nv_bfloat16* Wl = smb + 128 * KP2;
    __nv_bfloat16* Ah = smb + 2 * 128 * KP2;
    __nv_bfloat16* Al = Ah + NT * KP2;
    const int tid = threadIdx.x;
    const int lane = tid & 31, w = tid >> 5;
    const int wm = w >> 3, wg = w & 7;
    const int jb = wg * 16;

    for (int idx = tid; idx < 128 * 32; idx += 512) {
        int r = idx >> 5, c4 = idx & 31;
        float4 v = ((const float4*)(W + (size_t)r * wstride))[c4];
        bf16split4(v, (unsigned*)&Wh[r * KP2 + c4 * 4], (unsigned*)&Wl[r * KP2 + c4 * 4]);
    }

    const unsigned a_lane = (((lane & 15) * KP2) + (((lane >> 4) & 1) << 3)) * 2;
    const unsigned b_lane = ((((lane & 7) + (((lane >> 4) & 1) << 3)) * KP2)
                             + (((lane >> 3) & 1) << 3)) * 2;
    const unsigned sAh = (unsigned)__cvta_generic_to_shared(Ah) + a_lane + wm * 16 * KP2 * 2;
    const unsigned sAl = (unsigned)__cvta_generic_to_shared(Al) + a_lane + wm * 16 * KP2 * 2;
    const unsigned sWh = (unsigned)__cvta_generic_to_shared(Wh) + b_lane + (unsigned)jb * KP2 * 2;
    const unsigned sWl = (unsigned)__cvta_generic_to_shared(Wl) + b_lane + (unsigned)jb * KP2 * 2;

    const int stride = gridDim.x * NT;
    int t0 = blockIdx.x * NT;
    float4 pre[2];
    if (t0 < n) {
        int lim4 = min(NT, n - t0) * 32;
#pragma unroll
        for (int i = 0; i < 2; ++i) {
            int idx = tid + i * 512;
            pre[i] = (idx < lim4) ? ((const float4*)(A + (size_t)t0 * 128))[idx]
                                  : make_float4(0.f, 0.f, 0.f, 0.f);
        }
    }
    __syncthreads();

    for (; t0 < n; t0 += stride) {
        int cnt = min(NT, n - t0);
#pragma unroll
        for (int i = 0; i < 2; ++i) {
            int idx = tid + i * 512;
            int node = idx >> 5, kk = (idx & 31) << 2;
            bf16split4(pre[i], (unsigned*)&Ah[node * KP2 + kk], (unsigned*)&Al[node * KP2 + kk]);
        }
        __syncthreads();
        int tn = t0 + stride;
        if (tn < n) {
            int lim4 = min(NT, n - tn) * 32;
#pragma unroll
            for (int i = 0; i < 2; ++i) {
                int idx = tid + i * 512;
                pre[i] = (idx < lim4) ? ((const float4*)(A + (size_t)tn * 128))[idx]
                                      : make_float4(0.f, 0.f, 0.f, 0.f);
            }
        }

        float acc[2][4];
#pragma unroll
        for (int c = 0; c < 2; ++c)
#pragma unroll
            for (int e = 0; e < 4; ++e) acc[c][e] = 0.f;

#pragma unroll
        for (int ks = 0; ks < 8; ++ks) {
            const unsigned kb = ks * 32;
            unsigned ah[4], al[4], bh[4], bl[4];
            ldm4(ah, sAh + kb);
            ldm4(al, sAl + kb);
            ldm4(bh, sWh + kb);
            ldm4(bl, sWl + kb);
            mma16816(acc[0], ah, bh + 0);
            mma16816(acc[0], ah, bl + 0);
            mma16816(acc[0], al, bh + 0);
            mma16816(acc[1], ah, bh + 2);
            mma16816(acc[1], ah, bl + 2);
            mma16816(acc[1], al, bh + 2);
        }

        const int rbase = wm * 16 + (lane >> 2);
        const int colb = (lane & 3) * 2;
#pragma unroll
        for (int half = 0; half < 2; ++half) {
            int rl = rbase + half * 8;
            if (rl < cnt) {
                size_t node = (size_t)(t0 + rl);
#pragma unroll
                for (int sub = 0; sub < 2; ++sub) {
                    int j = jb + sub * 8 + colb;
                    float2 res;
#pragma unroll
                    for (int e = 0; e < 2; ++e) {
                        float r = acc[sub][half * 2 + e] + (bias ? __ldg(&bias[j + e]) : 0.f);
                        if (ACT == 1) r = (r >= 0.f) ? r : 0.01f * r;
                        else if (ACT == 2) r = fmaxf(r, 0.f);
                        else if (ACT == 3) r = (r > 0.f) ? r : expm1f(r);
                        if (e == 0) res.x = r; else res.y = r;
                    }
                    *(float2*)&out[node * 128 + j] = res;
                }
            }
        }
        __syncthreads();
    }
}

// ---------------- dense3m: GRU-gate GEMM on tensor cores (split-bf16, prefetch)
template <int EPI>
__global__ void __launch_bounds__(512) dense3m_kernel(
    const float* __restrict__ A, const float* __restrict__ W,
    const float* __restrict__ bias, float* __restrict__ out,
    const float* __restrict__ gi, int n)
{
    constexpr int KP2 = 136;
    constexpr int NT = 32;
    extern __shared__ __nv_bfloat16 smb[];
    __nv_bfloat16* Wh = smb;
    __nv_bfloat16* Wl = smb + 384 * KP2;
    __nv_bfloat16* Ah = smb + 2 * 384 * KP2;
    __nv_bfloat16* Al = Ah + NT * KP2;
    const int tid = threadIdx.x;
    const int lane = tid & 31, w = tid >> 5;
    const int wm = w >> 3, wg = w & 7;
    const int jb = wg * 16;

    for (int idx = tid; idx < 384 * 32; idx += 512) {
        float4 v = ((const float4*)W)[idx];
        int r = idx >> 5, kk = (idx & 31) << 2;
        bf16split4(v, (unsigned*)&Wh[r * KP2 + kk], (unsigned*)&Wl[r * KP2 + kk]);
    }

    const unsigned a_lane = (((lane & 15) * KP2) + (((lane >> 4) & 1) << 3)) * 2;
    const unsigned b_lane = ((((lane & 7) + (((lane >> 4) & 1) << 3)) * KP2)
                             + (((lane >> 3) & 1) << 3)) * 2;
    const unsigned sAh = (unsigned)__cvta_generic_to_shared(Ah) + a_lane + wm * 16 * KP2 * 2;
    const unsigned sAl = (unsigned)__cvta_generic_to_shared(Al) + a_lane + wm * 16 * KP2 * 2;
    const unsigned sWh = (unsigned)__cvta_generic_to_shared(Wh) + b_lane;
    const unsigned sWl = (unsigned)__cvta_generic_to_shared(Wl) + b_lane;

    const int stride = gridDim.x * NT;
    int t0 = blockIdx.x * NT;
    float4 pre[2];
    if (t0 < n) {
        int lim4 = min(NT, n - t0) * 32;
#pragma unroll
        for (int i = 0; i < 2; ++i) {
            int idx = tid + i * 512;
            pre[i] = (idx < lim4) ? ((const float4*)(A + (size_t)t0 * 128))[idx]
                                  : make_float4(0.f, 0.f, 0.f, 0.f);
        }
    }
    __syncthreads();

    for (; t0 < n; t0 += stride) {
        int cnt = min(NT, n - t0);
#pragma unroll
        for (int i = 0; i < 2; ++i) {
            int idx = tid + i * 512;
            int node = idx >> 5, kk = (idx & 31) << 2;
            bf16split4(pre[i], (unsigned*)&Ah[node * KP2 + kk], (unsigned*)&Al[node * KP2 + kk]);
        }
        __syncthreads();
        int tn = t0 + stride;
        if (tn < n) {
            int lim4 = min(NT, n - tn) * 32;
#pragma unroll
            for (int i = 0; i < 2; ++i) {
                int idx = tid + i * 512;
                pre[i] = (idx < lim4) ? ((const float4*)(A + (size_t)tn * 128))[idx]
                                      : make_float4(0.f, 0.f, 0.f, 0.f);
            }
        }

        float acc[6][4];
#pragma unroll
        for (int c = 0; c < 6; ++c)
#pragma unroll
            for (int e = 0; e < 4; ++e) acc[c][e] = 0.f;

#pragma unroll
        for (int ks = 0; ks < 8; ++ks) {
            const unsigned kb = ks * 32;
            unsigned ah[4], al[4];
            ldm4(ah, sAh + kb);
            ldm4(al, sAl + kb);
#pragma unroll
            for (int pb = 0; pb < 3; ++pb) {
                const unsigned nb = (unsigned)(jb + pb * 128) * KP2 * 2 + kb;
                unsigned bh[4], bl[4];
                ldm4(bh, sWh + nb);
                ldm4(bl, sWl + nb);
                mma16816(acc[pb * 2 + 0], ah, bh + 0);
                mma16816(acc[pb * 2 + 0], ah, bl + 0);
                mma16816(acc[pb * 2 + 0], al, bh + 0);
                mma16816(acc[pb * 2 + 1], ah, bh + 2);
                mma16816(acc[pb * 2 + 1], ah, bl + 2);
                mma16816(acc[pb * 2 + 1], al, bh + 2);
            }
        }

        const int rbase = wm * 16 + (lane >> 2);
        const int colb = (lane & 3) * 2;
#pragma unroll
        for (int half = 0; half < 2; ++half) {
            int rl = rbase + half * 8;
            if (rl < cnt) {
                size_t node = (size_t)(t0 + rl);
                if (EPI == 0) {
#pragma unroll
                    for (int pb = 0; pb < 3; ++pb)
#pragma unroll
                        for (int sub = 0; sub < 2; ++sub) {
                            int gate = jb + pb * 128 + sub * 8 + colb;
                            float2 v;
                            v.x = acc[pb * 2 + sub][half * 2 + 0] + __ldg(&bias[gate]);
                            v.y = acc[pb * 2 + sub][half * 2 + 1] + __ldg(&bias[gate + 1]);
                            *(float2*)&out[node * 384 + gate] = v;
                        }
                } else {
#pragma unroll
                    for (int sub = 0; sub < 2; ++sub) {
                        int j = jb + sub * 8 + colb;
                        float2 res;
#pragma unroll
                        for (int e = 0; e < 2; ++e) {
                            int je = j + e;
                            float hr = acc[sub][half * 2 + e] + __ldg(&bias[je]);
                            float hz = acc[2 + sub][half * 2 + e] + __ldg(&bias[128 + je]);
                            float hn = acc[4 + sub][half * 2 + e] + __ldg(&bias[256 + je]);
                            float r = sigm(gi[node * 384 + je] + hr);
                            float z = sigm(gi[node * 384 + 128 + je] + hz);
                            float nn = tanhf(gi[node * 384 + 256 + je] + r * hn);
                            float hv = A[node * 128 + je];
                            float o = fmaxf((1.f - z) * nn + z * hv, 0.f);
                            if (e == 0) res.x = o; else res.y = o;
                        }
                        *(float2*)&out[node * 128 + j] = res;
                    }
                }
            }
        }
        __syncthreads();
    }
}

// ---------------- nd gather (CSR, depth-2, static registers) ----------------
__global__ void __launch_bounds__(256) nd_gather_kernel(
    const float* __restrict__ p, const float* __restrict__ ea,
    const int* __restrict__ src, const int* __restrict__ off,
    const int* __restrict__ eid, const float* __restrict__ w1,
    float* __restrict__ tsum)
{
    __shared__ float W1b[16 * 128];
    const int tid = threadIdx.x;
    for (int idx = tid; idx < 16 * 128; idx += 256) {
        int k = idx >> 7, j = idx & 127;
        W1b[idx] = w1[j * 144 + 128 + k];
    }
    __syncthreads();
    int n = blockIdx.x * 8 + (tid >> 5);
    if (n >= NN) return;
    int lane = tid & 31;
    int beg = off[n], end = off[n + 1];
    float4 acc = make_float4(0.f, 0.f, 0.f, 0.f);
    const float4* W1b4 = (const float4*)W1b;
    const float4* p4 = (const float4*)p;

    float4 v0, v1;
    float ea0 = 0.f, ea1 = 0.f;
    if (beg < end) {
        int ed = __ldg(&eid[beg]);
        int s = __ldg(&src[ed]);
        ea0 = (lane < 16) ? __ldg(&ea[(size_t)ed * 16 + lane]) : 0.f;
        v0 = __ldg(&p4[(size_t)s * 32 + lane]);
    }
    if (beg + 1 < end) {
        int ed = __ldg(&eid[beg + 1]);
        int s = __ldg(&src[ed]);
        ea1 = (lane < 16) ? __ldg(&ea[(size_t)ed * 16 + lane]) : 0.f;
        v1 = __ldg(&p4[(size_t)s * 32 + lane]);
    }
    int e = beg;
    for (; e + 1 < end; e += 2) {
        float4 tA = v0; float eA = ea0;
        float4 tB = v1; float eB = ea1;
        if (e + 2 < end) {
            int ed = __ldg(&eid[e + 2]);
            int s = __ldg(&src[ed]);
            ea0 = (lane < 16) ? __ldg(&ea[(size_t)ed * 16 + lane]) : 0.f;
            v0 = __ldg(&p4[(size_t)s * 32 + lane]);
        }
        if (e + 3 < end) {
            int ed = __ldg(&eid[e + 3]);
            int s = __ldg(&src[ed]);
            ea1 = (lane < 16) ? __ldg(&ea[(size_t)ed * 16 + lane]) : 0.f;
            v1 = __ldg(&p4[(size_t)s * 32 + lane]);
        }
#pragma unroll
        for (int k = 0; k < 16; ++k) {
            float ek = __shfl_sync(0xFFFFFFFFu, eA, k);
            float4 w = W1b4[k * 32 + lane];
            tA.x += ek * w.x; tA.y += ek * w.y; tA.z += ek * w.z; tA.w += ek * w.w;
        }
        tA.x = (tA.x >= 0.f) ? tA.x : 0.01f * tA.x;
        tA.y = (tA.y >= 0.f) ? tA.y : 0.01f * tA.y;
        tA.z = (tA.z >= 0.f) ? tA.z : 0.01f * tA.z;
        tA.w = (tA.w >= 0.f) ? tA.w : 0.01f * tA.w;
        acc.x += tA.x; acc.y += tA.y; acc.z += tA.z; acc.w += tA.w;
#pragma unroll
        for (int k = 0; k < 16; ++k) {
            float ek = __shfl_sync(0xFFFFFFFFu, eB, k);
            float4 w = W1b4[k * 32 + lane];
            tB.x += ek * w.x; tB.y += ek * w.y; tB.z += ek * w.z; tB.w += ek * w.w;
        }
        tB.x = (tB.x >= 0.f) ? tB.x : 0.01f * tB.x;
        tB.y = (tB.y >= 0.f) ? tB.y : 0.01f * tB.y;
        tB.z = (tB.z >= 0.f) ? tB.z : 0.01f * tB.z;
        tB.w = (tB.w >= 0.f) ? tB.w : 0.01f * tB.w;
        acc.x += tB.x; acc.y += tB.y; acc.z += tB.z; acc.w += tB.w;
    }
    if (e < end) {
        float4 tA = v0; float eA = ea0;
#pragma unroll
        for (int k = 0; k < 16; ++k) {
            float ek = __shfl_sync(0xFFFFFFFFu, eA, k);
            float4 w = W1b4[k * 32 + lane];
            tA.x += ek * w.x; tA.y += ek * w.y; tA.z += ek * w.z; tA.w += ek * w.w;
        }
        tA.x = (tA.x >= 0.f) ? tA.x : 0.01f * tA.x;
        tA.y = (tA.y >= 0.f) ? tA.y : 0.01f * tA.y;
        tA.z = (tA.z >= 0.f) ? tA.z : 0.01f * tA.z;
        tA.w = (tA.w >= 0.f) ? tA.w : 0.01f * tA.w;
        acc.x += tA.x; acc.y += tA.y; acc.z += tA.z; acc.w += tA.w;
    }
    ((float4*)tsum)[(size_t)n * 32 + lane] = acc;
}

// ---------------- GAT attention dots ----------------
__global__ void attn_dots_kernel(const float* __restrict__ xp, const float* __restrict__ asrc,
                                 const float* __restrict__ adst, float* __restrict__ as_,
                                 float* __restrict__ ad_) {
    int n = (blockIdx.x * blockDim.x + threadIdx.x) >> 5;
    int lane = threadIdx.x & 31;
    if (n >= NN) return;
    float4 v = ((const float4*)xp)[(size_t)n * 32 + lane];
    float4 w1 = ((const float4*)asrc)[lane];
    float4 w2 = ((const float4*)adst)[lane];
    float sa = v.x * w1.x + v.y * w1.y + v.z * w1.z + v.w * w1.w;
    float sd = v.x * w2.x + v.y * w2.y + v.z * w2.z + v.w * w2.w;
#pragma unroll
    for (int o = 16; o; o >>= 1) {
        sa += __shfl_xor_sync(0xFFFFFFFFu, sa, o);
        sd += __shfl_xor_sync(0xFFFFFFFFu, sd, o);
    }
    if (lane == 0) { as_[n] = sa; ad_[n] = sd; }
}

// ---------------- GAT gather (CSR, online softmax, depth-2 static) ---------
__global__ void __launch_bounds__(256) gat_gather_kernel(
    const int* __restrict__ src, const int* __restrict__ off, const int* __restrict__ eid,
    const float* __restrict__ as_, const float* __restrict__ ad_,
    const float* __restrict__ xp, const float* __restrict__ bias,
    float* __restrict__ hout)
{
    int n = blockIdx.x * 8 + (threadIdx.x >> 5);
    if (n >= NN) return;
    int lane = threadIdx.x & 31;
    int beg = off[n], end = off[n + 1];
    float adn = ad_[n];
    float m = -INFINITY, den = 0.f;
    float4 acc = make_float4(0.f, 0.f, 0.f, 0.f);
    const float4* xp4 = (const float4*)xp;

    float4 v0, v1;
    float av0 = 0.f, av1 = 0.f;
    if (beg < end) {
        int s = __ldg(&src[__ldg(&eid[beg])]);
        av0 = __ldg(&as_[s]);
        v0 = __ldg(&xp4[(size_t)s * 32 + lane]);
    }
    if (beg + 1 < end) {
        int s = __ldg(&src[__ldg(&eid[beg + 1])]);
        av1 = __ldg(&as_[s]);
        v1 = __ldg(&xp4[(size_t)s * 32 + lane]);
    }
    int e = beg;
    for (; e + 1 < end; e += 2) {
        float aA = av0 + adn; float4 vA = v0;
        float aB = av1 + adn; float4 vB = v1;
        if (e + 2 < end) {
            int s = __ldg(&src[__ldg(&eid[e + 2])]);
            av0 = __ldg(&as_[s]);
            v0 = __ldg(&xp4[(size_t)s * 32 + lane]);
        }
        if (e + 3 < end) {
            int s = __ldg(&src[__ldg(&eid[e + 3])]);
            av1 = __ldg(&as_[s]);
            v1 = __ldg(&xp4[(size_t)s * 32 + lane]);
        }
        aA = (aA >= 0.f) ? aA : 0.01f * aA;
        if (aA > m) {
            float f = __expf(m - aA);
            den *= f;
            acc.x *= f; acc.y *= f; acc.z *= f; acc.w *= f;
            m = aA;
        }
        {
            float wv = __expf(aA - m);
            den += wv;
            acc.x += wv * vA.x; acc.y += wv * vA.y; acc.z += wv * vA.z; acc.w += wv * vA.w;
        }
        aB = (aB >= 0.f) ? aB : 0.01f * aB;
        if (aB > m) {
            float f = __expf(m - aB);
            den *= f;
            acc.x *= f; acc.y *= f; acc.z *= f; acc.w *= f;
            m = aB;
        }
        {
            float wv = __expf(aB - m);
            den += wv;
            acc.x += wv * vB.x; acc.y += wv * vB.y; acc.z += wv * vB.z; acc.w += wv * vB.w;
        }
    }
    if (e < end) {
        float aA = av0 + adn; float4 vA = v0;
        aA = (aA >= 0.f) ? aA : 0.01f * aA;
        if (aA > m) {
            float f = __expf(m - aA);
            den *= f;
            acc.x *= f; acc.y *= f; acc.z *= f; acc.w *= f;
            m = aA;
        }
        float wv = __expf(aA - m);
        den += wv;
        acc.x += wv * vA.x; acc.y += wv * vA.y; acc.z += wv * vA.z; acc.w += wv * vA.w;
    }
    float inv = (den > 0.f) ? 1.f / den : 0.f;
    float4 b = ((const float4*)bias)[lane];
    float4 r;
    r.x = acc.x * inv + b.x; r.y = acc.y * inv + b.y;
    r.z = acc.z * inv + b.z; r.w = acc.w * inv + b.w;
    r.x = (r.x > 0.f) ? r.x : expm1f(r.x);
    r.y = (r.y > 0.f) ? r.y : expm1f(r.y);
    r.z = (r.z > 0.f) ? r.z : expm1f(r.z);
    r.w = (r.w > 0.f) ? r.w : expm1f(r.w);
    ((float4*)hout)[(size_t)n * 32 + lane] = r;
}

// ---------------- readout ----------------
__global__ void __launch_bounds__(128) graph_agg_kernel(const float* __restrict__ xcur,
                                                        const int* __restrict__ batch,
                                                        float* __restrict__ agg,
                                                        float* __restrict__ outv) {
    int g = blockIdx.x;
    int lo, hi;
    {
        int l = 0, r = NN;
        while (l < r) { int m = (l + r) >> 1; if (batch[m] < g) l = m + 1; else r = m; }
        lo = l;
    }
    {
        int l = lo, r = NN;
        while (l < r) { int m = (l + r) >> 1; if (batch[m] < g + 1) l = m + 1; else r = m; }
        hi = l;
    }
    float s = 0.f;
    for (int n = lo; n < hi; ++n) s += xcur[(size_t)n * 128 + threadIdx.x];
    agg[g * 128 + threadIdx.x] = s;
    outv[g * 128 + threadIdx.x] = fmaxf(s, 0.f);
}

__global__ void add_kernel(const float* __restrict__ a, const float* __restrict__ b,
                           float* __restrict__ c, int n) {
    int t = blockIdx.x * blockDim.x + threadIdx.x;
    if (t < n) c[t] = a[t] + b[t];
}

__global__ void lstm_combine_kernel(const float* __restrict__ gi, const float* __restrict__ gh,
                                    const float* __restrict__ hc, float* __restrict__ out) {
    int t = blockIdx.x * blockDim.x + threadIdx.x;
    if (t >= NG * 128) return;
    int g = t >> 7, j = t & 127;
    size_t base = (size_t)g * 512;
    float gI = gi[base + j]       + gh[base + j];
    float gF = gi[base + 128 + j] + gh[base + 128 + j];
    float gG = gi[base + 256 + j] + gh[base + 256 + j];
    float gO = gi[base + 384 + j] + gh[base + 384 + j];
    float c = hc[t];
    float c2 = sigm(gF) * c + sigm(gI) * tanhf(gG);
    out[t] = sigm(gO) * tanhf(c2);
}

__global__ void final_kernel(const float* __restrict__ outv, const float* __restrict__ w,
                             const float* __restrict__ b, float* __restrict__ res) {
    int g = (blockIdx.x * blockDim.x + threadIdx.x) >> 5;
    int lane = threadIdx.x & 31;
    if (g >= NG) return;
    float4 v = ((const float4*)outv)[(size_t)g * 32 + lane];
    float4 ww = ((const float4*)w)[lane];
    float s = v.x * ww.x + v.y * ww.y + v.z * ww.z + v.w * ww.w;
#pragma unroll
    for (int o = 16; o; o >>= 1) s += __shfl_xor_sync(0xFFFFFFFFu, s, o);
    if (lane == 0) res[g] = s + b[0];
}

// ---------------- host ----------------
#define SM_J1K64  ((128 * 68 + 16 * 64) * 4)
#define SM_J1K128 ((128 * 132 + 16 * 128) * 4)
#define SM_M1     ((2 * 128 * 136 + 2 * 32 * 136) * 2)
#define SM_M3     ((2 * 384 * 136 + 2 * 32 * 136) * 2)

extern "C" void kernel_launch(void* const* d_in, const int* in_sizes, int n_in,
                              void* d_out, int out_size) {
    const float* x        = (const float*)d_in[0];
    const int*   ei       = (const int*)  d_in[1];
    const float* ea       = (const float*)d_in[2];
    const int*   batch    = (const int*)  d_in[3];
    const float* lin1_w   = (const float*)d_in[4];
    const float* lin1_b   = (const float*)d_in[5];
    const float* nd_lin1w = (const float*)d_in[6];
    const float* nd_lin2w = (const float*)d_in[7];
    const float* nd_bias  = (const float*)d_in[8];
    const float* gru0_wih = (const float*)d_in[9];
    const float* gru0_whh = (const float*)d_in[10];
    const float* gru0_bih = (const float*)d_in[11];
    const float* gru0_bhh = (const float*)d_in[12];
    const float* gat_w    = (const float*)d_in[13];
    const float* gat_asrc = (const float*)d_in[14];
    const float* gat_adst = (const float*)d_in[15];
    const float* gat_b    = (const float*)d_in[16];
    const float* gru_wih  = (const float*)d_in[17];
    const float* gru_whh  = (const float*)d_in[18];
    const float* gru_bih  = (const float*)d_in[19];
    const float* gru_bhh  = (const float*)d_in[20];
    const float* gin_w    = (const float*)d_in[21];
    const float* gin_b    = (const float*)d_in[22];
    const float* lstm_wih = (const float*)d_in[23];
    const float* lstm_whh = (const float*)d_in[24];
    const float* lstm_bih = (const float*)d_in[25];
    const float* lstm_bhh = (const float*)d_in[26];
    const float* lin2_w   = (const float*)d_in[27];
    const float* lin2_b   = (const float*)d_in[28];
    float* out = (float*)d_out;

    const int* src = ei;
    const int* dst = ei + NE;

    float *px1, *pp, *ph, *pxc, *pgi, *pas, *pad;
    float *pagg, *pgout, *pghh, *pgtmp, *pggi, *pggh;
    int *pcnt, *poff, *ppos, *peid, *ppart;
    cudaGetSymbolAddress((void**)&px1, f_x1);
    cudaGetSymbolAddress((void**)&pp, f_p);
    cudaGetSymbolAddress((void**)&ph, f_h);
    cudaGetSymbolAddress((void**)&pxc, f_xcur);
    cudaGetSymbolAddress((void**)&pgi, f_gi);
    cudaGetSymbolAddress((void**)&pas, f_as);
    cudaGetSymbolAddress((void**)&pad, f_ad);
    cudaGetSymbolAddress((void**)&pagg, g_agg);
    cudaGetSymbolAddress((void**)&pgout, g_out);
    cudaGetSymbolAddress((void**)&pghh, g_hh);
    cudaGetSymbolAddress((void**)&pgtmp, g_tmp);
    cudaGetSymbolAddress((void**)&pggi, g_gi);
    cudaGetSymbolAddress((void**)&pggh, g_gh);
    cudaGetSymbolAddress((void**)&pcnt, c_cnt);
    cudaGetSymbolAddress((void**)&poff, c_off);
    cudaGetSymbolAddress((void**)&ppos, c_pos);
    cudaGetSymbolAddress((void**)&peid, c_eid);
    cudaGetSymbolAddress((void**)&ppart, c_part);

    cudaFuncSetAttribute((const void*)dense_kernel<64, 1>, cudaFuncAttributeMaxDynamicSharedMemorySize, SM_J1K64);
    cudaFuncSetAttribute((const void*)dense_kernel<128, 0>, cudaFuncAttributeMaxDynamicSharedMemorySize, SM_J1K128);
    cudaFuncSetAttribute((const void*)dense_kernel<128, 3>, cudaFuncAttributeMaxDynamicSharedMemorySize, SM_J1K128);
    cudaFuncSetAttribute((const void*)dense1m_kernel<0>, cudaFuncAttributeMaxDynamicSharedMemorySize, SM_M1);
    cudaFuncSetAttribute((const void*)dense1m_kernel<3>, cudaFuncAttributeMaxDynamicSharedMemorySize, SM_M1);
    cudaFuncSetAttribute((const void*)dense3m_kernel<0>, cudaFuncAttributeMaxDynamicSharedMemorySize, SM_M3);
    cudaFuncSetAttribute((const void*)dense3m_kernel<1>, cudaFuncAttributeMaxDynamicSharedMemorySize, SM_M3);

    const int GP1b = 592;
    const int GPD1 = 296;
    const int GP3 = 148;
    const int NPART = (NN + 1023) / 1024;
    const int tilesG = (NG + 15) / 16;
    const int ZB = 256;

    // 0) x1 = leaky(x @ lin1_w.T + b)
    dense_kernel<64, 1><<<dim3(GP1b, 1), 128, SM_J1K64>>>(x, lin1_w, lin1_b, px1, NN, 128, 64);
    // 1-2) CSR phase A
    zero_i_kernel<<<(NN + ZB - 1) / ZB, ZB>>>(pcnt, NN);
    hist_kernel<<<(NE + ZB - 1) / ZB, ZB>>>(dst, pcnt);
    // 3) p = x1 @ W1a.T   <-- PROFILED
    dense1m_kernel<0><<<GPD1, 512, SM_M1>>>(px1, nd_lin1w, nullptr, pp, NN, 144);
    // 4-7) CSR phase B
    scan_part_kernel<<<NPART, 256>>>(pcnt, ppart);
    scan_mid_kernel<<<1, 32>>>(ppart, NPART);
    scan_final_kernel<<<NPART, 256>>>(pcnt, ppart, poff, ppos);
    fill_kernel<<<(NE + ZB - 1) / ZB, ZB>>>(dst, ppos, peid);
    // tsum
    nd_gather_kernel<<<(NN + 7) / 8, 256>>>(pp, ea, src, poff, peid, nd_lin1w, pgi);
    // h = elu(tsum @ W2.T + nd_bias)
    dense1m_kernel<3><<<GPD1, 512, SM_M1>>>(pgi, nd_lin2w, nd_bias, ph, NN, 128);
    // GRU0
    dense3m_kernel<0><<<GP3, 512, SM_M3>>>(ph, gru0_wih, gru0_bih, pgi, nullptr, NN);
    dense3m_kernel<1><<<GP3, 512, SM_M3>>>(px1, gru0_whh, gru0_bhh, pxc, pgi, NN);

    // GAT layers
    for (int l = 0; l < 2; ++l) {
        dense1m_kernel<0><<<GPD1, 512, SM_M1>>>(pxc, gat_w + (size_t)l * 128 * 128, nullptr, pp, NN, 128);
        attn_dots_kernel<<<(NN * 32 + ZB - 1) / ZB, ZB>>>(pp, gat_asrc + l * 128, gat_adst + l * 128, pas, pad);
        gat_gather_kernel<<<(NN + 7) / 8, 256>>>(src, poff, peid, pas, pad, pp, gat_b + l * 128, ph);
        dense3m_kernel<0><<<GP3, 512, SM_M3>>>(ph, gru_wih + (size_t)l * 384 * 128, gru_bih + l * 384, pgi, nullptr, NN);
        dense3m_kernel<1><<<GP3, 512, SM_M3>>>(pxc, gru_whh + (size_t)l * 384 * 128, gru_bhh + l * 384, pxc, pgi, NN);
    }

    // readout (round-12 multi-kernel form)
    graph_agg_kernel<<<NG, 128>>>(pxc, batch, pagg, pgout);
    for (int t = 0; t < 2; ++t) {
        add_kernel<<<(NG * 128 + ZB - 1) / ZB, ZB>>>(pgout, pagg, pgtmp, NG * 128);
        dense_kernel<128, 3><<<dim3(tilesG, 1), 128, SM_J1K128>>>(pgtmp, gin_w, gin_b, pghh, NG, 128, 128);
        dense_kernel<128, 0><<<dim3(tilesG, 4), 128, SM_J1K128>>>(pgout, lstm_wih, lstm_bih, pggi, NG, 512, 128);
        dense_kernel<128, 0><<<dim3(tilesG, 4), 128, SM_J1K128>>>(pghh, lstm_whh, lstm_bhh, pggh, NG, 512, 128);
        lstm_combine_kernel<<<(NG * 128 + ZB - 1) / ZB, ZB>>>(pggi, pggh, pghh, pgout);
    }
    final_kernel<<<(NG * 32 + 127) / 128, 128>>>(pgout, lin2_w, lin2_b, out);
}